// round 11
// baseline (speedup 1.0000x reference)
#include <cuda_runtime.h>
#include <math.h>

#define NN 8192
#define RT 16                      // rows per group
#define NGROUPS (NN / RT)          // 512
#define PHASES 16
#define NUNITS ((NGROUPS / 2) * PHASES)   // 256 balanced pairs * 16 phases = 4096
#define BLOCK 1024
#define WPB 32
#define GRID 148
#define NLGW ((GRID - 1) * WPB)    // 4704 worker warps (block 147 does ranks)
#define NCHUNK (NN / 128)          // 64 chunks of 128 j's
#define NBINS 4096
#define NPAIRS 33550336.0          // N*(N-1)/2
#define SMEM_BYTES 65536           // e[] (32KB) | rank scratch (64KB)

// Partials (all slots rewritten every launch) + completion counter that the
// last block resets to 0 -> deterministic under graph replay. No allocations.
__device__ double2 g_part[GRID];
__device__ int     g_done = 0;

__device__ __forceinline__ unsigned key_of(float t) {
    unsigned k = __float_as_uint(t);
    return (k & 0x80000000u) ? ~k : (k | 0x80000000u);  // monotone float->uint
}

__global__ void __launch_bounds__(BLOCK, 1)
rrl_kernel(const float* __restrict__ pred, const float* __restrict__ target,
           float* __restrict__ out) {
    extern __shared__ char smem[];
    const int tid  = threadIdx.x;
    const int warp = tid >> 5, lane = tid & 31;
    const int b    = blockIdx.x;

    float acc_l2 = 0.0f;   // sum log2(e_i+e_j)   (blocks 0..146)
    float acc_ps = 0.0f;   // sum p_k * rank_k    (block 147)

    if (b < GRID - 1) {
        // ---------- log-sum blocks: only e[] needed ----------
        float* s_e = (float*)smem;
        for (int i = tid; i < NN; i += BLOCK) s_e[i] = __expf(pred[i]);
        __syncthreads();

        const int W  = b * WPB + warp;
        const int lo = W * NUNITS / NLGW;
        const int hi = (W + 1) * NUNITS / NLGW;
        if (hi > lo) {                       // this warp owns unit `lo`
            const int pairid = lo >> 4;
            const int phase  = lo & 15;
            #pragma unroll 1
            for (int sgrp = 0; sgrp < 2; ++sgrp) {
                const int g     = sgrp ? (NGROUPS - 1 - pairid) : pairid;
                const int rbase = g * RT;
                float er[RT];
                #pragma unroll
                for (int r = 0; r < RT; ++r) er[r] = s_e[rbase + r];
                const int c0 = rbase >> 7;           // chunk holding the triangle
                int c = c0 + ((phase - c0) & 15);
                #pragma unroll 1
                for (; c < NCHUNK; c += PHASES) {
                    const int jb = (c << 7) + 4 * lane;
                    const float4 e4 = *(const float4*)(s_e + jb);
                    const float ejq[4] = {e4.x, e4.y, e4.z, e4.w};
                    if (c != c0) {
                        // clean chunk: all 16 rows valid for every j
                        #pragma unroll
                        for (int q = 0; q < 4; ++q) {
                            const float ej = ejq[q];
                            float m0 = (er[0]+ej)*(er[1]+ej);
                            float m1 = (er[2]+ej)*(er[3]+ej);
                            float m2 = (er[4]+ej)*(er[5]+ej);
                            float m3 = (er[6]+ej)*(er[7]+ej);
                            float m4 = (er[8]+ej)*(er[9]+ej);
                            float m5 = (er[10]+ej)*(er[11]+ej);
                            float m6 = (er[12]+ej)*(er[13]+ej);
                            float m7 = (er[14]+ej)*(er[15]+ej);
                            acc_l2 += __log2f(((m0*m1)*(m2*m3))*((m4*m5)*(m6*m7)));
                        }
                    } else {
                        // triangle chunk: invalid pairs contribute se=1 (log2=0)
                        #pragma unroll
                        for (int q = 0; q < 4; ++q) {
                            const int   j  = jb + q;
                            const float ej = ejq[q];
                            float se[RT];
                            #pragma unroll
                            for (int r = 0; r < RT; ++r)
                                se[r] = (j > rbase + r) ? (er[r] + ej) : 1.0f;
                            float p = ((se[0]*se[1])*(se[2]*se[3]))
                                    * ((se[4]*se[5])*(se[6]*se[7]))
                                    * (((se[8]*se[9])*(se[10]*se[11]))
                                    *  ((se[12]*se[13])*(se[14]*se[15])));
                            acc_l2 += __log2f(p);
                        }
                    }
                }
            }
        }
    } else {
        // ---------- rank block: sum_ps = sum p_k * #{t_j < t_k} ----------
        unsigned* skey = (unsigned*)smem;                       // [NN]
        unsigned* offs = (unsigned*)(smem + NN * 4);            // [NBINS]
        unsigned* cnts = (unsigned*)(smem + NN * 4 + NBINS * 4);// [NBINS]

        for (int i = tid; i < NBINS; i += BLOCK) cnts[i] = 0;
        __syncthreads();
        for (int k = tid; k < NN; k += BLOCK)
            atomicAdd(&cnts[key_of(target[k]) >> 20], 1u);
        __syncthreads();
        // exclusive prefix sum over 4096 bins (4 per thread)
        {
            unsigned v[4], s = 0;
            #pragma unroll
            for (int q = 0; q < 4; ++q) { v[q] = cnts[4*tid + q]; s += v[q]; }
            const unsigned ts = s;
            #pragma unroll
            for (int o = 1; o < 32; o <<= 1) {
                unsigned n = __shfl_up_sync(0xffffffffu, s, o);
                if (lane >= o) s += n;
            }
            __shared__ unsigned wtot[WPB];
            if (lane == 31) wtot[warp] = s;
            __syncthreads();
            if (warp == 0) {
                unsigned x = wtot[lane];
                #pragma unroll
                for (int o = 1; o < 32; o <<= 1) {
                    unsigned n = __shfl_up_sync(0xffffffffu, x, o);
                    if (lane >= o) x += n;
                }
                wtot[lane] = x;
            }
            __syncthreads();
            unsigned run = (warp ? wtot[warp - 1] : 0u) + (s - ts);
            #pragma unroll
            for (int q = 0; q < 4; ++q) { offs[4*tid + q] = run; run += v[q]; }
        }
        __syncthreads();
        for (int i = tid; i < NBINS; i += BLOCK) cnts[i] = 0;
        __syncthreads();
        for (int k = tid; k < NN; k += BLOCK) {
            unsigned key = key_of(target[k]);
            unsigned bn  = key >> 20;
            unsigned pos = offs[bn] + atomicAdd(&cnts[bn], 1u);
            skey[pos] = key;
        }
        __syncthreads();
        // rank = elements in smaller bins + strictly-smaller within own bin.
        // Order-invariant w.r.t. scatter order -> deterministic.
        for (int k = tid; k < NN; k += BLOCK) {
            const unsigned key = key_of(target[k]);
            const unsigned bn  = key >> 20;
            const unsigned lo2 = offs[bn], n = cnts[bn];
            unsigned r = lo2;
            for (unsigned s2 = lo2; s2 < lo2 + n; ++s2)
                r += (skey[s2] < key) ? 1u : 0u;
            acc_ps += pred[k] * (float)r;
        }
    }

    // ---------- block reduction ----------
    #pragma unroll
    for (int o = 16; o; o >>= 1) {
        acc_l2 += __shfl_xor_sync(0xffffffffu, acc_l2, o);
        acc_ps += __shfl_xor_sync(0xffffffffu, acc_ps, o);
    }
    __shared__ float rl[WPB], rp[WPB];
    if (lane == 0) { rl[warp] = acc_l2; rp[warp] = acc_ps; }
    __syncthreads();
    if (warp == 0) {
        float a = rl[lane], p = rp[lane];       // WPB == 32: all lanes valid
        #pragma unroll
        for (int o = 16; o; o >>= 1) {
            a += __shfl_xor_sync(0xffffffffu, a, o);
            p += __shfl_xor_sync(0xffffffffu, p, o);
        }
        if (lane == 0) g_part[b] = make_double2((double)a, (double)p);
    }

    // ---------- last-block final combine ----------
    __threadfence();
    __shared__ int s_last;
    if (tid == 0) s_last = (atomicAdd(&g_done, 1) == GRID - 1) ? 1 : 0;
    __syncthreads();
    if (s_last) {
        double A = 0.0, P = 0.0;
        if (tid < GRID) { double2 v = g_part[tid]; A = v.x; P = v.y; }
        #pragma unroll
        for (int o = 16; o; o >>= 1) {
            A += __shfl_down_sync(0xffffffffu, A, o);
            P += __shfl_down_sync(0xffffffffu, P, o);
        }
        __shared__ double fa[WPB], fp[WPB];
        if (lane == 0) { fa[warp] = A; fp[warp] = P; }
        __syncthreads();
        if (tid == 0) {
            double AA = 0.0, PP = 0.0;
            #pragma unroll
            for (int w = 0; w < WPB; ++w) { AA += fa[w]; PP += fp[w]; }
            const double LN2 = 0.6931471805599453;
            out[0] = (float)((LN2 * AA - PP) / NPAIRS);
            g_done = 0;   // reset for next graph replay
        }
    }
}

extern "C" void kernel_launch(void* const* d_in, const int* in_sizes, int n_in,
                              void* d_out, int out_size) {
    const float* pred   = (const float*)d_in[0];
    const float* target = (const float*)d_in[1];
    float* out = (float*)d_out;
    (void)in_sizes; (void)n_in; (void)out_size;

    cudaFuncSetAttribute(rrl_kernel,
                         cudaFuncAttributeMaxDynamicSharedMemorySize, SMEM_BYTES);

    rrl_kernel<<<GRID, BLOCK, SMEM_BYTES>>>(pred, target, out);
}